// round 15
// baseline (speedup 1.0000x reference)
#include <cuda_runtime.h>
#include <cuda_fp16.h>
#include <math.h>

#define BATCH 256
#define C1_IN 3
#define C1_OUT 6
#define H_IN 250
#define C1_H 124          // conv1 out H/W
#define P1_H 123          // pool1 out H/W
#define C2_OUT 15
#define C2_H 62           // conv2 out H/W
#define P2_H 61           // pool2 out H/W
#define K_FC1 55815       // 15*61*61
#define N_FC1 120
#define N_FC2 84
#define KSPLIT 148
#define KCHUNK 378        // ceil(55815/148)

typedef unsigned long long ull;

// Scratch (static device globals — allocation-free)
__device__ __half g_conv1[(size_t)BATCH * C1_OUT * C1_H * C1_H];   // 47.2 MB
__device__ __half g_conv2[(size_t)BATCH * C2_OUT * C2_H * C2_H];   // 29.5 MB
__device__ float  g_fc1_part[KSPLIT][BATCH * N_FC1];               // 18.2 MB
__device__ float  g_red2[4][BATCH * N_FC1];                         // 491 KB
__device__ float  g_h1[BATCH * N_FC1];                              // 120 KB

// packed f32x2 helpers
#define BPACK(dst, f) asm("mov.b64 %0, {%1, %1};" : "=l"(dst) : "r"(__float_as_uint(f)))
#define PACK2(dst, lo, hi) asm("mov.b64 %0, {%1, %2};" : "=l"(dst) : "r"(__float_as_uint(lo)), "r"(__float_as_uint(hi)))
#define FMA2(acc, a, b) asm("fma.rn.f32x2 %0, %1, %2, %0;" : "+l"(acc) : "l"(a), "l"(b))
#define LO(v) __uint_as_float((unsigned)((v) & 0xffffffffULL))
#define HI(v) __uint_as_float((unsigned)((v) >> 32))

// ---------------------------------------------------------------------------
// conv1 v15: best measured combo.
//  - FLAT unrolled loader (v11: high load-MLP; the warp-per-row loader was a
//    measured ~+21us regression)
//  - CONFLICT-FREE compute mapping (v13: tx=tid&31, warp lanes on one row;
//    measured -3.4us)
//  - 32x16 tile, 37.3KB smem, 6 blocks/SM (occ 71% config), tap-major LDS.128
//    packed weights.
// ---------------------------------------------------------------------------
#define C1_PP 40
#define C1_ROWS_ 35
#define C1_PLANE (3 * C1_ROWS_ * C1_PP)        // 4200
#define C1_W_OFF (2 * C1_PLANE)                // 8400 floats -> 16B-aligned
#define C1_SMEM_BYTES (C1_W_OFF * 4 + 450 * 8 + 64)

__global__ __launch_bounds__(256, 6) void conv1_kernel(const float* __restrict__ x,
                                                       const float* __restrict__ w1,
                                                       const float* __restrict__ b1) {
    extern __shared__ float sm1[];
    ull* Wp = (ull*)(sm1 + C1_W_OFF);          // [75 taps][6 oc]
    float* Bias = (float*)(Wp + 450);

    const int b = blockIdx.z;
    const int ox0 = blockIdx.x * 32, oy0 = blockIdx.y * 16;
    const int tid = threadIdx.x;
    const int tx = tid & 31, ty = tid >> 5;    // 32 x 8 (conflict-free mapping)

    for (int i = tid; i < 450; i += 256) {
        ull p; BPACK(p, w1[(i % 6) * 75 + (i / 6)]);
        Wp[i] = p;
    }
    if (tid < 6) Bias[tid] = b1[tid];

    const int iy0 = oy0 * 2 - 1, ix0 = ox0 * 2 - 1;
    const float* xb = x + (size_t)b * C1_IN * H_IN * H_IN;

    // FLAT loader (v11): unroll-4, high MLP
#pragma unroll 4
    for (int idx = tid; idx < 3 * C1_ROWS_ * 67; idx += 256) {
        int c = idx / (C1_ROWS_ * 67), r = idx % (C1_ROWS_ * 67);
        int y = r / 67, u = r % 67;
        int iy = iy0 + y, ix = ix0 + u;
        float v = 0.f;
        if (iy >= 0 && iy < H_IN && ix >= 0 && ix < H_IN)
            v = xb[(c * H_IN + iy) * H_IN + ix];
        sm1[(u & 1) * C1_PLANE + (c * C1_ROWS_ + y) * C1_PP + (u >> 1)] = v;
    }
    __syncthreads();

    ull acc[6];                                // (px@y=ty, px@y=ty+8) per oc
#pragma unroll
    for (int oc = 0; oc < 6; oc++) acc[oc] = 0ULL;

#pragma unroll
    for (int c = 0; c < 3; c++) {
#pragma unroll
        for (int ky = 0; ky < 5; ky++) {
            const float* rE0 = sm1 + (c * C1_ROWS_ + ty * 2 + ky) * C1_PP;
            const float* rE1 = sm1 + (c * C1_ROWS_ + (ty + 8) * 2 + ky) * C1_PP;
#pragma unroll
            for (int kx = 0; kx < 5; kx++) {
                const int po = (kx & 1) ? C1_PLANE : 0;
                int j = tx + (kx >> 1);
                float s0 = (rE0 + po)[j];
                float s1 = (rE1 + po)[j];
                ull sp; PACK2(sp, s0, s1);
                const ulonglong2* wv =
                    (const ulonglong2*)(Wp + ((c * 5 + ky) * 5 + kx) * 6);
                ulonglong2 wa = wv[0], wb = wv[1], wc = wv[2];
                FMA2(acc[0], sp, wa.x); FMA2(acc[1], sp, wa.y);
                FMA2(acc[2], sp, wb.x); FMA2(acc[3], sp, wb.y);
                FMA2(acc[4], sp, wc.x); FMA2(acc[5], sp, wc.y);
            }
        }
    }

    const int ox = ox0 + tx;
    const int oyA = oy0 + ty, oyB = oy0 + ty + 8;
    if (ox < C1_H) {
#pragma unroll
        for (int oc = 0; oc < 6; oc++) {
            __half* dst = g_conv1 + (size_t)(b * C1_OUT + oc) * C1_H * C1_H;
            float bias = Bias[oc];
            if (oyA < C1_H) dst[oyA * C1_H + ox] = __float2half(fmaxf(LO(acc[oc]) + bias, 0.f));
            if (oyB < C1_H) dst[oyB * C1_H + ox] = __float2half(fmaxf(HI(acc[oc]) + bias, 0.f));
        }
    }
}

// ---------------------------------------------------------------------------
// conv2: IDENTICAL to rounds 11-14.
// ---------------------------------------------------------------------------
#define C2_PITCH 68
#define C2_ROWS 35
#define C2_P_ELEMS (6 * C2_ROWS * C2_PITCH)
#define C2_W_ULL (54 * 16)
#define C2_SMEM_BYTES (C2_W_ULL * 8 + C2_P_ELEMS * 2 + 64)

__global__ __launch_bounds__(256, 4) void conv2_kernel(const float* __restrict__ w2,
                                                       const float* __restrict__ b2) {
    extern __shared__ ull sm2u[];
    ull* Wp = sm2u;                            // [54 taps][16 slots (15 oc)]
    __half* P = (__half*)(sm2u + C2_W_ULL);    // [6][35][68]
    float* Bias = (float*)((char*)P + C2_P_ELEMS * 2);

    const int b = blockIdx.z;
    const int ox0 = blockIdx.x * 32, oy0 = blockIdx.y * 16;
    const int tid = threadIdx.x;
    const int tx = tid & 31, ty = tid >> 5;

    for (int i = tid; i < C2_W_ULL; i += 256) {
        int oc = i & 15, tap = i >> 4;
        float v = (oc < 15) ? w2[oc * 54 + tap] : 0.f;
        ull p; BPACK(p, v);
        Wp[i] = p;
    }
    if (tid < 15) Bias[tid] = b2[tid];

    const int py0 = oy0 * 2 - 1, px0 = ox0 * 2 - 1;
    const __half* cb = g_conv1 + (size_t)b * C1_OUT * C1_H * C1_H;

#pragma unroll 4
    for (int idx = tid; idx < C2_P_ELEMS; idx += 256) {
        int c = idx / (C2_ROWS * C2_PITCH), r = idx % (C2_ROWS * C2_PITCH);
        int y = r / C2_PITCH, u = r % C2_PITCH;
        int py = py0 + y, px = px0 + u;
        float v = 0.f;
        if (u < 67 && py >= 0 && py < P1_H && px >= 0 && px < P1_H) {
            const __half* p = cb + (c * C1_H + py) * C1_H + px;
            float v00 = __half2float(p[0]),     v01 = __half2float(p[1]);
            float v10 = __half2float(p[C1_H]),  v11 = __half2float(p[C1_H + 1]);
            v = fmaxf(fmaxf(v00, v01), fmaxf(v10, v11));
        }
        P[idx] = __float2half(v);
    }
    __syncthreads();

    ull acc[15];
#pragma unroll
    for (int oc = 0; oc < 15; oc++) acc[oc] = 0ULL;

#pragma unroll
    for (int c = 0; c < 6; c++) {
        const __half* Pc = P + c * C2_ROWS * C2_PITCH;
#pragma unroll
        for (int ky = 0; ky < 3; ky++) {
            const __half* r0 = Pc + (ty * 2 + ky) * C2_PITCH;
            const __half* r1 = Pc + ((ty + 8) * 2 + ky) * C2_PITCH;
#pragma unroll
            for (int kx = 0; kx < 3; kx++) {
                float s0 = __half2float(r0[tx * 2 + kx]);
                float s1 = __half2float(r1[tx * 2 + kx]);
                ull sp; PACK2(sp, s0, s1);
                const ull* wt = Wp + (c * 9 + ky * 3 + kx) * 16;
                const ulonglong2* wv = (const ulonglong2*)wt;
                ulonglong2 wA = wv[0], wB = wv[1], wC = wv[2], wD = wv[3];
                ulonglong2 wE = wv[4], wF = wv[5], wG = wv[6];
                ull w14 = wt[14];
                FMA2(acc[0], sp, wA.x);  FMA2(acc[1], sp, wA.y);
                FMA2(acc[2], sp, wB.x);  FMA2(acc[3], sp, wB.y);
                FMA2(acc[4], sp, wC.x);  FMA2(acc[5], sp, wC.y);
                FMA2(acc[6], sp, wD.x);  FMA2(acc[7], sp, wD.y);
                FMA2(acc[8], sp, wE.x);  FMA2(acc[9], sp, wE.y);
                FMA2(acc[10], sp, wF.x); FMA2(acc[11], sp, wF.y);
                FMA2(acc[12], sp, wG.x); FMA2(acc[13], sp, wG.y);
                FMA2(acc[14], sp, w14);
            }
        }
    }

    const int ox = ox0 + tx;
    const int oyA = oy0 + ty, oyB = oy0 + ty + 8;
    if (ox < C2_H) {
#pragma unroll
        for (int oc = 0; oc < 15; oc++) {
            __half* dst = g_conv2 + (size_t)(b * C2_OUT + oc) * C2_H * C2_H;
            float bias = Bias[oc];
            if (oyA < C2_H) dst[oyA * C2_H + ox] = __float2half(fmaxf(LO(acc[oc]) + bias, 0.f));
            if (oyB < C2_H) dst[oyB * C2_H + ox] = __float2half(fmaxf(HI(acc[oc]) + bias, 0.f));
        }
    }
}

// ---------------------------------------------------------------------------
// FC1 tensor-core GEMM: BK=32 version (twice-measured ~11us faster than BK16).
// ---------------------------------------------------------------------------
#define FC1_BK 32

#define LDSM_X4(r0, r1, r2, r3, addr) \
    asm volatile("ldmatrix.sync.aligned.m8n8.x4.shared.b16 {%0,%1,%2,%3}, [%4];" \
        : "=r"(r0), "=r"(r1), "=r"(r2), "=r"(r3) : "r"(addr))

#define LDSM_X2_T(r0, r1, addr) \
    asm volatile("ldmatrix.sync.aligned.m8n8.x2.trans.shared.b16 {%0,%1}, [%2];" \
        : "=r"(r0), "=r"(r1) : "r"(addr))

#define MMA_16816(c, a0, a1, a2, a3, b0, b1) \
    asm volatile("mma.sync.aligned.m16n8k16.row.col.f32.f16.f16.f32 " \
        "{%0,%1,%2,%3}, {%4,%5,%6,%7}, {%8,%9}, {%0,%1,%2,%3};" \
        : "+f"(c[0]), "+f"(c[1]), "+f"(c[2]), "+f"(c[3]) \
        : "r"(a0), "r"(a1), "r"(a2), "r"(a3), "r"(b0), "r"(b1))

__global__ __launch_bounds__(512) void fc1_mma_kernel(const float* __restrict__ fc1_w) {
    __shared__ __half As[256][40];     // 32 k + pad 8
    __shared__ __half Bs[FC1_BK][136];

    const int tid = threadIdx.x;
    const int lane = tid & 31, w = tid >> 5;
    const int k0 = blockIdx.x * KCHUNK;
    const int kend = min(k0 + KCHUNK, K_FC1);

    float acc[15][4];
#pragma unroll
    for (int nt = 0; nt < 15; nt++)
#pragma unroll
        for (int i = 0; i < 4; i++) acc[nt][i] = 0.f;

    const int kk_a = tid & 31;
    const int rbase = tid >> 5;

    __half ra[16];
    float rb[8];

    auto loadA = [&](int kb) {
        int k = kb + kk_a;
        if (k < kend) {
            int c = k / 3721;
            int rem = k - c * 3721;
            int y = rem / 61;
            int xx = rem - y * 61;
            const __half* base = g_conv2 + ((size_t)c * C2_H + y) * C2_H + xx;
#pragma unroll
            for (int i = 0; i < 16; i++) {
                int mrow = rbase + 16 * i;
                const __half* p = base + (size_t)mrow * (C2_OUT * C2_H * C2_H);
                float v00 = __half2float(p[0]),     v01 = __half2float(p[1]);
                float v10 = __half2float(p[C2_H]),  v11 = __half2float(p[C2_H + 1]);
                ra[i] = __float2half(fmaxf(fmaxf(v00, v01), fmaxf(v10, v11)));
            }
        } else {
#pragma unroll
            for (int i = 0; i < 16; i++) ra[i] = __float2half(0.f);
        }
    };
    auto loadB = [&](int kb) {
#pragma unroll
        for (int i = 0; i < 8; i++) {
            int idx = tid + i * 512;
            rb[i] = 0.f;
            if (idx < 3840) {
                int n = idx >> 5;
                int kk = idx & 31;
                int k = kb + kk;
                if (k < kend) rb[i] = fc1_w[(size_t)n * K_FC1 + k];
            }
        }
    };
    auto stsAB = [&]() {
#pragma unroll
        for (int i = 0; i < 16; i++)
            As[rbase + 16 * i][kk_a] = ra[i];
#pragma unroll
        for (int i = 0; i < 8; i++) {
            int idx = tid + i * 512;
            if (idx < 3840) Bs[idx & 31][idx >> 5] = __float2half(rb[i]);
        }
    };

    const unsigned aaddr0 = (unsigned)__cvta_generic_to_shared(
        &As[w * 16 + (lane & 15)][(lane >> 4) * 8]);
    const unsigned aaddr1 = (unsigned)__cvta_generic_to_shared(
        &As[w * 16 + (lane & 15)][16 + (lane >> 4) * 8]);
    const unsigned baddr0 = (unsigned)__cvta_generic_to_shared(
        &Bs[lane & 15][0]);
    const unsigned baddr1 = (unsigned)__cvta_generic_to_shared(
        &Bs[16 + (lane & 15)][0]);

    loadA(k0);
    loadB(k0);

    for (int kb = k0; kb < kend; kb += FC1_BK) {
        stsAB();
        __syncthreads();
        if (kb + FC1_BK < kend) { loadA(kb + FC1_BK); loadB(kb + FC1_BK); }

        unsigned a0, a1, a2, a3, c0, c1, c2, c3;
        LDSM_X4(a0, a1, a2, a3, aaddr0);
        LDSM_X4(c0, c1, c2, c3, aaddr1);
#pragma unroll
        for (int nt = 0; nt < 15; nt++) {
            unsigned b0, b1, d0, d1;
            LDSM_X2_T(b0, b1, baddr0 + nt * 16);
            LDSM_X2_T(d0, d1, baddr1 + nt * 16);
            MMA_16816(acc[nt], a0, a1, a2, a3, b0, b1);
            MMA_16816(acc[nt], c0, c1, c2, c3, d0, d1);
        }
        __syncthreads();
    }

    const int r0 = w * 16 + (lane >> 2);
    const int cb = (lane & 3) * 2;
    float* dst = g_fc1_part[blockIdx.x];
#pragma unroll
    for (int nt = 0; nt < 15; nt++) {
        int cc = nt * 8 + cb;
        dst[r0 * N_FC1 + cc]           = acc[nt][0];
        dst[r0 * N_FC1 + cc + 1]       = acc[nt][1];
        dst[(r0 + 8) * N_FC1 + cc]     = acc[nt][2];
        dst[(r0 + 8) * N_FC1 + cc + 1] = acc[nt][3];
    }
}

// ---------------------------------------------------------------------------
// reduce: two-stage (rounds 12-14).
// ---------------------------------------------------------------------------
__global__ __launch_bounds__(128) void reduce1_kernel() {
    const int part = blockIdx.y;
    const int idx = blockIdx.x * 128 + threadIdx.x;
    const int j0 = part * 37;
    float s = 0.f;
#pragma unroll 8
    for (int j = 0; j < 37; j++)
        s += g_fc1_part[j0 + j][idx];
    g_red2[part][idx] = s;
}

__global__ __launch_bounds__(128) void reduce2_kernel(const float* __restrict__ fc1_b) {
    const int idx = blockIdx.x * 128 + threadIdx.x;
    float s = fc1_b[idx % N_FC1]
            + g_red2[0][idx] + g_red2[1][idx]
            + g_red2[2][idx] + g_red2[3][idx];
    g_h1[idx] = fmaxf(s, 0.f);
}

// ---------------------------------------------------------------------------
// Head: reads precomputed h1; FC2+ReLU, FC3, quantum sim, softmax.
// ---------------------------------------------------------------------------
__global__ void head_kernel(const float* __restrict__ fc2_w,
                            const float* __restrict__ fc2_b,
                            const float* __restrict__ fc3_w,
                            const float* __restrict__ fc3_b,
                            const float* __restrict__ qw,
                            float* __restrict__ out) {
    const int b = blockIdx.x;
    __shared__ float h1[N_FC1];
    __shared__ float h2[N_FC2];
    __shared__ float ang[4];
    const int t = threadIdx.x;

    if (t < N_FC1) h1[t] = g_h1[b * N_FC1 + t];
    __syncthreads();

    if (t < N_FC2) {
        float a = fc2_b[t];
#pragma unroll 8
        for (int k = 0; k < N_FC1; k++) a += h1[k] * fc2_w[t * N_FC1 + k];
        h2[t] = fmaxf(a, 0.f);
    }
    __syncthreads();

    if (t < 4) {
        float a = fc3_b[t];
#pragma unroll 4
        for (int k = 0; k < N_FC2; k++) a += h2[k] * fc3_w[t * N_FC2 + k];
        ang[t] = a;
    }
    __syncthreads();

    if (t == 0) {
        float sr[16], si[16];
#pragma unroll
        for (int i = 0; i < 16; i++) { sr[i] = 0.f; si[i] = 0.f; }
        sr[0] = 1.f;

#pragma unroll
        for (int q = 0; q < 4; q++) {
            float th = ang[q] * 0.5f;
            float c = cosf(th), s = sinf(th);
            const int bit = 1 << (3 - q);
#pragma unroll
            for (int i0 = 0; i0 < 16; i0++) {
                if (i0 & bit) continue;
                int i1 = i0 | bit;
                float a0r = sr[i0], a0i = si[i0], a1r = sr[i1], a1i = si[i1];
                sr[i0] = c * a0r + s * a1i;  si[i0] = c * a0i - s * a1r;
                sr[i1] = c * a1r + s * a0i;  si[i1] = c * a1i - s * a0r;
            }
        }
        int w = 0;
#pragma unroll
        for (int d = 0; d < 2; d++) {
#pragma unroll
            for (int q = 0; q < 4; q++) {
                float th = qw[w++] * 0.5f;
                float c = cosf(th), s = sinf(th);
                const int bit = 1 << (3 - q);
#pragma unroll
                for (int i0 = 0; i0 < 16; i0++) {
                    if (i0 & bit) continue;
                    int i1 = i0 | bit;
                    float a0r = sr[i0], a0i = si[i0], a1r = sr[i1], a1i = si[i1];
                    sr[i0] = c * a0r - s * a1r;  si[i0] = c * a0i - s * a1i;
                    sr[i1] = s * a0r + c * a1r;  si[i1] = s * a0i + c * a1i;
                }
            }
#pragma unroll
            for (int q = 0; q < 3; q++) {
                const int m1 = 1 << (3 - q), m2 = 1 << (2 - q);
#pragma unroll
                for (int i = 0; i < 16; i++)
                    if ((i & m1) && (i & m2)) { sr[i] = -sr[i]; si[i] = -si[i]; }
            }
        }
        float l0 = 0.f, l1 = 0.f;
#pragma unroll
        for (int i = 0; i < 16; i++) {
            float p = sr[i] * sr[i] + si[i] * si[i];
            l0 += (i & 8) ? -p : p;
            l1 += (i & 4) ? -p : p;
        }
        float m = fmaxf(l0, l1);
        float e0 = __expf(l0 - m), e1 = __expf(l1 - m);
        float inv = 1.f / (e0 + e1);
        out[b * 2 + 0] = e0 * inv;
        out[b * 2 + 1] = e1 * inv;
    }
}

// ---------------------------------------------------------------------------
extern "C" void kernel_launch(void* const* d_in, const int* in_sizes, int n_in,
                              void* d_out, int out_size) {
    const float* x     = (const float*)d_in[0];
    const float* w1    = (const float*)d_in[1];
    const float* b1    = (const float*)d_in[2];
    const float* w2    = (const float*)d_in[3];
    const float* b2    = (const float*)d_in[4];
    const float* fc1_w = (const float*)d_in[5];
    const float* fc1_b = (const float*)d_in[6];
    const float* fc2_w = (const float*)d_in[7];
    const float* fc2_b = (const float*)d_in[8];
    const float* fc3_w = (const float*)d_in[9];
    const float* fc3_b = (const float*)d_in[10];
    const float* qw    = (const float*)d_in[11];
    float* out = (float*)d_out;

    cudaFuncSetAttribute(conv1_kernel, cudaFuncAttributeMaxDynamicSharedMemorySize, C1_SMEM_BYTES);
    cudaFuncSetAttribute(conv2_kernel, cudaFuncAttributeMaxDynamicSharedMemorySize, C2_SMEM_BYTES);

    conv1_kernel<<<dim3(4, 8, BATCH), 256, C1_SMEM_BYTES>>>(x, w1, b1);
    conv2_kernel<<<dim3(2, 4, BATCH), 256, C2_SMEM_BYTES>>>(w2, b2);
    fc1_mma_kernel<<<KSPLIT, 512>>>(fc1_w);
    reduce1_kernel<<<dim3(240, 4), 128>>>();
    reduce2_kernel<<<240, 128>>>(fc1_b);
    head_kernel<<<BATCH, 128>>>(fc2_w, fc2_b, fc3_w, fc3_b, qw, out);
}

// round 16
// speedup vs baseline: 1.4369x; 1.4369x over previous
#include <cuda_runtime.h>
#include <cuda_fp16.h>
#include <math.h>

#define BATCH 256
#define C1_IN 3
#define C1_OUT 6
#define H_IN 250
#define C1_H 124          // conv1 out H/W
#define P1_H 123          // pool1 out H/W
#define C2_OUT 15
#define C2_H 62           // conv2 out H/W
#define P2_H 61           // pool2 out H/W
#define K_FC1 55815       // 15*61*61
#define N_FC1 120
#define N_FC2 84
#define KSPLIT 148
#define KCHUNK 378        // ceil(55815/148)

typedef unsigned long long ull;

// Scratch (static device globals — allocation-free)
__device__ __half g_conv1[(size_t)BATCH * C1_OUT * C1_H * C1_H];   // 47.2 MB
__device__ __half g_conv2[(size_t)BATCH * C2_OUT * C2_H * C2_H];   // 29.5 MB
__device__ float  g_fc1_part[KSPLIT][BATCH * N_FC1];               // 18.2 MB
__device__ float  g_h1[BATCH * N_FC1];                              // 120 KB

// packed f32x2 helpers
#define BPACK(dst, f) asm("mov.b64 %0, {%1, %1};" : "=l"(dst) : "r"(__float_as_uint(f)))
#define PACK2(dst, lo, hi) asm("mov.b64 %0, {%1, %2};" : "=l"(dst) : "r"(__float_as_uint(lo)), "r"(__float_as_uint(hi)))
#define FMA2(acc, a, b) asm("fma.rn.f32x2 %0, %1, %2, %0;" : "+l"(acc) : "l"(a), "l"(b))
#define LO(v) __uint_as_float((unsigned)((v) & 0xffffffffULL))
#define HI(v) __uint_as_float((unsigned)((v) >> 32))

// ---------------------------------------------------------------------------
// conv1: EXACT R11 version (best total 381.7us). De-interleaved even/odd-x
// planes + tap-major LDS.128 packed weights; flat unroll-4 loader;
// 16x-group mapping (tx=tid&15). 6 blocks/SM.
// ---------------------------------------------------------------------------
#define C1_PP 40
#define C1_ROWS_ 35
#define C1_PLANE (3 * C1_ROWS_ * C1_PP)        // 4200
#define C1_W_OFF (2 * C1_PLANE)                // 8400 floats -> 16B-aligned
#define C1_SMEM_BYTES (C1_W_OFF * 4 + 450 * 8 + 64)

__global__ __launch_bounds__(256, 6) void conv1_kernel(const float* __restrict__ x,
                                                       const float* __restrict__ w1,
                                                       const float* __restrict__ b1) {
    extern __shared__ float sm1[];
    ull* Wp = (ull*)(sm1 + C1_W_OFF);          // [75 taps][6 oc]
    float* Bias = (float*)(Wp + 450);

    const int b = blockIdx.z;
    const int ox0 = blockIdx.x * 32, oy0 = blockIdx.y * 16;
    const int tid = threadIdx.x;
    const int tx = tid & 15, ty = tid >> 4;

    // tap-major: Wp[tap*6 + oc] = dup(w1[oc*75 + tap])
    for (int i = tid; i < 450; i += 256) {
        ull p; BPACK(p, w1[(i % 6) * 75 + (i / 6)]);
        Wp[i] = p;
    }
    if (tid < 6) Bias[tid] = b1[tid];

    const int iy0 = oy0 * 2 - 1, ix0 = ox0 * 2 - 1;
    const float* xb = x + (size_t)b * C1_IN * H_IN * H_IN;

#pragma unroll 4
    for (int idx = tid; idx < 3 * C1_ROWS_ * 67; idx += 256) {
        int c = idx / (C1_ROWS_ * 67), r = idx % (C1_ROWS_ * 67);
        int y = r / 67, u = r % 67;
        int iy = iy0 + y, ix = ix0 + u;
        float v = 0.f;
        if (iy >= 0 && iy < H_IN && ix >= 0 && ix < H_IN)
            v = xb[(c * H_IN + iy) * H_IN + ix];
        sm1[(u & 1) * C1_PLANE + (c * C1_ROWS_ + y) * C1_PP + (u >> 1)] = v;
    }
    __syncthreads();

    ull acc[6];
#pragma unroll
    for (int oc = 0; oc < 6; oc++) acc[oc] = 0ULL;

#pragma unroll
    for (int c = 0; c < 3; c++) {
#pragma unroll
        for (int ky = 0; ky < 5; ky++) {
            const float* re = sm1 + (c * C1_ROWS_ + ty * 2 + ky) * C1_PP;
            const float* ro = re + C1_PLANE;
#pragma unroll
            for (int kx = 0; kx < 5; kx++) {
                const float* pl = (kx & 1) ? ro : re;
                int j = tx + (kx >> 1);
                float s0 = pl[j];
                float s1 = pl[j + 16];
                ull sp; PACK2(sp, s0, s1);
                const ulonglong2* wv =
                    (const ulonglong2*)(Wp + ((c * 5 + ky) * 5 + kx) * 6);
                ulonglong2 wa = wv[0], wb = wv[1], wc = wv[2];
                FMA2(acc[0], sp, wa.x); FMA2(acc[1], sp, wa.y);
                FMA2(acc[2], sp, wb.x); FMA2(acc[3], sp, wb.y);
                FMA2(acc[4], sp, wc.x); FMA2(acc[5], sp, wc.y);
            }
        }
    }

    const int oy = oy0 + ty;
    const int oxA = ox0 + tx, oxB = ox0 + tx + 16;
    if (oy < C1_H) {
#pragma unroll
        for (int oc = 0; oc < 6; oc++) {
            __half* dst = g_conv1 + ((size_t)(b * C1_OUT + oc) * C1_H + oy) * C1_H;
            float bias = Bias[oc];
            if (oxA < C1_H) dst[oxA] = __float2half(fmaxf(LO(acc[oc]) + bias, 0.f));
            if (oxB < C1_H) dst[oxB] = __float2half(fmaxf(HI(acc[oc]) + bias, 0.f));
        }
    }
}

// ---------------------------------------------------------------------------
// conv2: EXACT R11 version. fp16 pooled tile + tap-major packed weights.
// ---------------------------------------------------------------------------
#define C2_PITCH 68
#define C2_ROWS 35
#define C2_P_ELEMS (6 * C2_ROWS * C2_PITCH)
#define C2_W_ULL (54 * 16)
#define C2_SMEM_BYTES (C2_W_ULL * 8 + C2_P_ELEMS * 2 + 64)

__global__ __launch_bounds__(256, 4) void conv2_kernel(const float* __restrict__ w2,
                                                       const float* __restrict__ b2) {
    extern __shared__ ull sm2u[];
    ull* Wp = sm2u;                            // [54 taps][16 slots (15 oc)]
    __half* P = (__half*)(sm2u + C2_W_ULL);    // [6][35][68]
    float* Bias = (float*)((char*)P + C2_P_ELEMS * 2);

    const int b = blockIdx.z;
    const int ox0 = blockIdx.x * 32, oy0 = blockIdx.y * 16;
    const int tid = threadIdx.x;
    const int tx = tid & 31, ty = tid >> 5;

    for (int i = tid; i < C2_W_ULL; i += 256) {
        int oc = i & 15, tap = i >> 4;
        float v = (oc < 15) ? w2[oc * 54 + tap] : 0.f;
        ull p; BPACK(p, v);
        Wp[i] = p;
    }
    if (tid < 15) Bias[tid] = b2[tid];

    const int py0 = oy0 * 2 - 1, px0 = ox0 * 2 - 1;
    const __half* cb = g_conv1 + (size_t)b * C1_OUT * C1_H * C1_H;

#pragma unroll 4
    for (int idx = tid; idx < C2_P_ELEMS; idx += 256) {
        int c = idx / (C2_ROWS * C2_PITCH), r = idx % (C2_ROWS * C2_PITCH);
        int y = r / C2_PITCH, u = r % C2_PITCH;
        int py = py0 + y, px = px0 + u;
        float v = 0.f;
        if (u < 67 && py >= 0 && py < P1_H && px >= 0 && px < P1_H) {
            const __half* p = cb + (c * C1_H + py) * C1_H + px;
            float v00 = __half2float(p[0]),     v01 = __half2float(p[1]);
            float v10 = __half2float(p[C1_H]),  v11 = __half2float(p[C1_H + 1]);
            v = fmaxf(fmaxf(v00, v01), fmaxf(v10, v11));
        }
        P[idx] = __float2half(v);
    }
    __syncthreads();

    ull acc[15];
#pragma unroll
    for (int oc = 0; oc < 15; oc++) acc[oc] = 0ULL;

#pragma unroll
    for (int c = 0; c < 6; c++) {
        const __half* Pc = P + c * C2_ROWS * C2_PITCH;
#pragma unroll
        for (int ky = 0; ky < 3; ky++) {
            const __half* r0 = Pc + (ty * 2 + ky) * C2_PITCH;
            const __half* r1 = Pc + ((ty + 8) * 2 + ky) * C2_PITCH;
#pragma unroll
            for (int kx = 0; kx < 3; kx++) {
                float s0 = __half2float(r0[tx * 2 + kx]);
                float s1 = __half2float(r1[tx * 2 + kx]);
                ull sp; PACK2(sp, s0, s1);
                const ull* wt = Wp + (c * 9 + ky * 3 + kx) * 16;
                const ulonglong2* wv = (const ulonglong2*)wt;
                ulonglong2 wA = wv[0], wB = wv[1], wC = wv[2], wD = wv[3];
                ulonglong2 wE = wv[4], wF = wv[5], wG = wv[6];
                ull w14 = wt[14];
                FMA2(acc[0], sp, wA.x);  FMA2(acc[1], sp, wA.y);
                FMA2(acc[2], sp, wB.x);  FMA2(acc[3], sp, wB.y);
                FMA2(acc[4], sp, wC.x);  FMA2(acc[5], sp, wC.y);
                FMA2(acc[6], sp, wD.x);  FMA2(acc[7], sp, wD.y);
                FMA2(acc[8], sp, wE.x);  FMA2(acc[9], sp, wE.y);
                FMA2(acc[10], sp, wF.x); FMA2(acc[11], sp, wF.y);
                FMA2(acc[12], sp, wG.x); FMA2(acc[13], sp, wG.y);
                FMA2(acc[14], sp, w14);
            }
        }
    }

    const int ox = ox0 + tx;
    const int oyA = oy0 + ty, oyB = oy0 + ty + 8;
    if (ox < C2_H) {
#pragma unroll
        for (int oc = 0; oc < 15; oc++) {
            __half* dst = g_conv2 + (size_t)(b * C2_OUT + oc) * C2_H * C2_H;
            float bias = Bias[oc];
            if (oyA < C2_H) dst[oyA * C2_H + ox] = __float2half(fmaxf(LO(acc[oc]) + bias, 0.f));
            if (oyB < C2_H) dst[oyB * C2_H + ox] = __float2half(fmaxf(HI(acc[oc]) + bias, 0.f));
        }
    }
}

// ---------------------------------------------------------------------------
// FC1 tensor-core GEMM: EXACT R11 version (BM=256, BK=16, 512 threads).
// ---------------------------------------------------------------------------
#define FC1_BK 16

#define LDSM_X4(r0, r1, r2, r3, addr) \
    asm volatile("ldmatrix.sync.aligned.m8n8.x4.shared.b16 {%0,%1,%2,%3}, [%4];" \
        : "=r"(r0), "=r"(r1), "=r"(r2), "=r"(r3) : "r"(addr))

#define LDSM_X2_T(r0, r1, addr) \
    asm volatile("ldmatrix.sync.aligned.m8n8.x2.trans.shared.b16 {%0,%1}, [%2];" \
        : "=r"(r0), "=r"(r1) : "r"(addr))

#define MMA_16816(c, a0, a1, a2, a3, b0, b1) \
    asm volatile("mma.sync.aligned.m16n8k16.row.col.f32.f16.f16.f32 " \
        "{%0,%1,%2,%3}, {%4,%5,%6,%7}, {%8,%9}, {%0,%1,%2,%3};" \
        : "+f"(c[0]), "+f"(c[1]), "+f"(c[2]), "+f"(c[3]) \
        : "r"(a0), "r"(a1), "r"(a2), "r"(a3), "r"(b0), "r"(b1))

__global__ __launch_bounds__(512) void fc1_mma_kernel(const float* __restrict__ fc1_w) {
    __shared__ __half As[256][24];
    __shared__ __half Bs[FC1_BK][136];

    const int tid = threadIdx.x;
    const int lane = tid & 31, w = tid >> 5;   // 16 warps, one m16 slab each
    const int k0 = blockIdx.x * KCHUNK;
    const int kend = min(k0 + KCHUNK, K_FC1);

    float acc[15][4];
#pragma unroll
    for (int nt = 0; nt < 15; nt++)
#pragma unroll
        for (int i = 0; i < 4; i++) acc[nt][i] = 0.f;

    const int kk_a = tid & 15;                 // consecutive lanes -> consecutive k
    const int rbase = tid >> 4;                // 0..31

    __half ra[8];
    float rb[4];

    auto loadA = [&](int kb) {
        int k = kb + kk_a;
        if (k < kend) {
            int c = k / 3721;
            int rem = k - c * 3721;
            int y = rem / 61;
            int xx = rem - y * 61;
            const __half* base = g_conv2 + ((size_t)c * C2_H + y) * C2_H + xx;
#pragma unroll
            for (int i = 0; i < 8; i++) {
                int mrow = rbase + 32 * i;
                const __half* p = base + (size_t)mrow * (C2_OUT * C2_H * C2_H);
                float v00 = __half2float(p[0]),     v01 = __half2float(p[1]);
                float v10 = __half2float(p[C2_H]),  v11 = __half2float(p[C2_H + 1]);
                ra[i] = __float2half(fmaxf(fmaxf(v00, v01), fmaxf(v10, v11)));
            }
        } else {
#pragma unroll
            for (int i = 0; i < 8; i++) ra[i] = __float2half(0.f);
        }
    };
    auto loadB = [&](int kb) {
#pragma unroll
        for (int i = 0; i < 4; i++) {
            int idx = tid + i * 512;
            rb[i] = 0.f;
            if (idx < 1920) {
                int n = idx >> 4;
                int kk = idx & 15;
                int k = kb + kk;
                if (k < kend) rb[i] = fc1_w[(size_t)n * K_FC1 + k];
            }
        }
    };
    auto stsAB = [&]() {
#pragma unroll
        for (int i = 0; i < 8; i++)
            As[rbase + 32 * i][kk_a] = ra[i];
#pragma unroll
        for (int i = 0; i < 4; i++) {
            int idx = tid + i * 512;
            if (idx < 1920) Bs[idx & 15][idx >> 4] = __float2half(rb[i]);
        }
    };

    const unsigned aaddr = (unsigned)__cvta_generic_to_shared(
        &As[w * 16 + (lane & 15)][(lane >> 4) * 8]);
    const unsigned baddr0 = (unsigned)__cvta_generic_to_shared(
        &Bs[lane & 15][0]);

    loadA(k0);
    loadB(k0);

    for (int kb = k0; kb < kend; kb += FC1_BK) {
        stsAB();
        __syncthreads();
        if (kb + FC1_BK < kend) { loadA(kb + FC1_BK); loadB(kb + FC1_BK); }

        unsigned a0, a1, a2, a3;
        LDSM_X4(a0, a1, a2, a3, aaddr);
#pragma unroll
        for (int nt = 0; nt < 15; nt++) {
            unsigned b0, b1;
            LDSM_X2_T(b0, b1, baddr0 + nt * 16);
            MMA_16816(acc[nt], a0, a1, a2, a3, b0, b1);
        }
        __syncthreads();
    }

    const int r0 = w * 16 + (lane >> 2);
    const int cb = (lane & 3) * 2;
    float* dst = g_fc1_part[blockIdx.x];
#pragma unroll
    for (int nt = 0; nt < 15; nt++) {
        int cc = nt * 8 + cb;
        dst[r0 * N_FC1 + cc]           = acc[nt][0];
        dst[r0 * N_FC1 + cc + 1]       = acc[nt][1];
        dst[(r0 + 8) * N_FC1 + cc]     = acc[nt][2];
        dst[(r0 + 8) * N_FC1 + cc + 1] = acc[nt][3];
    }
}

// ---------------------------------------------------------------------------
// reduce v16: ONLY change vs R11 — 2 outputs/thread via float2 (half the
// load instructions, 2x MLP). 240 blocks x 64 threads = 15360 threads.
// ---------------------------------------------------------------------------
__global__ __launch_bounds__(64) void reduce_kernel(const float* __restrict__ fc1_b) {
    const int p = blockIdx.x * 64 + threadIdx.x;       // 0..15359
    const int idx = p * 2;
    float sx = fc1_b[idx % N_FC1];
    float sy = fc1_b[(idx + 1) % N_FC1];
#pragma unroll 8
    for (int j = 0; j < KSPLIT; j++) {
        float2 v = *(const float2*)&g_fc1_part[j][idx];
        sx += v.x; sy += v.y;
    }
    float2 r; r.x = fmaxf(sx, 0.f); r.y = fmaxf(sy, 0.f);
    *(float2*)&g_h1[idx] = r;
}

// ---------------------------------------------------------------------------
// Head: EXACT R11 version.
// ---------------------------------------------------------------------------
__global__ void head_kernel(const float* __restrict__ fc2_w,
                            const float* __restrict__ fc2_b,
                            const float* __restrict__ fc3_w,
                            const float* __restrict__ fc3_b,
                            const float* __restrict__ qw,
                            float* __restrict__ out) {
    const int b = blockIdx.x;
    __shared__ float h1[N_FC1];
    __shared__ float h2[N_FC2];
    __shared__ float ang[4];
    const int t = threadIdx.x;

    if (t < N_FC1) h1[t] = g_h1[b * N_FC1 + t];
    __syncthreads();

    if (t < N_FC2) {
        float a = fc2_b[t];
#pragma unroll 8
        for (int k = 0; k < N_FC1; k++) a += h1[k] * fc2_w[t * N_FC1 + k];
        h2[t] = fmaxf(a, 0.f);
    }
    __syncthreads();

    if (t < 4) {
        float a = fc3_b[t];
#pragma unroll 4
        for (int k = 0; k < N_FC2; k++) a += h2[k] * fc3_w[t * N_FC2 + k];
        ang[t] = a;
    }
    __syncthreads();

    if (t == 0) {
        float sr[16], si[16];
#pragma unroll
        for (int i = 0; i < 16; i++) { sr[i] = 0.f; si[i] = 0.f; }
        sr[0] = 1.f;

#pragma unroll
        for (int q = 0; q < 4; q++) {
            float th = ang[q] * 0.5f;
            float c = cosf(th), s = sinf(th);
            const int bit = 1 << (3 - q);
#pragma unroll
            for (int i0 = 0; i0 < 16; i0++) {
                if (i0 & bit) continue;
                int i1 = i0 | bit;
                float a0r = sr[i0], a0i = si[i0], a1r = sr[i1], a1i = si[i1];
                sr[i0] = c * a0r + s * a1i;  si[i0] = c * a0i - s * a1r;
                sr[i1] = c * a1r + s * a0i;  si[i1] = c * a1i - s * a0r;
            }
        }
        int w = 0;
#pragma unroll
        for (int d = 0; d < 2; d++) {
#pragma unroll
            for (int q = 0; q < 4; q++) {
                float th = qw[w++] * 0.5f;
                float c = cosf(th), s = sinf(th);
                const int bit = 1 << (3 - q);
#pragma unroll
                for (int i0 = 0; i0 < 16; i0++) {
                    if (i0 & bit) continue;
                    int i1 = i0 | bit;
                    float a0r = sr[i0], a0i = si[i0], a1r = sr[i1], a1i = si[i1];
                    sr[i0] = c * a0r - s * a1r;  si[i0] = c * a0i - s * a1i;
                    sr[i1] = s * a0r + c * a1r;  si[i1] = s * a0i + c * a1i;
                }
            }
#pragma unroll
            for (int q = 0; q < 3; q++) {
                const int m1 = 1 << (3 - q), m2 = 1 << (2 - q);
#pragma unroll
                for (int i = 0; i < 16; i++)
                    if ((i & m1) && (i & m2)) { sr[i] = -sr[i]; si[i] = -si[i]; }
            }
        }
        float l0 = 0.f, l1 = 0.f;
#pragma unroll
        for (int i = 0; i < 16; i++) {
            float p = sr[i] * sr[i] + si[i] * si[i];
            l0 += (i & 8) ? -p : p;
            l1 += (i & 4) ? -p : p;
        }
        float m = fmaxf(l0, l1);
        float e0 = __expf(l0 - m), e1 = __expf(l1 - m);
        float inv = 1.f / (e0 + e1);
        out[b * 2 + 0] = e0 * inv;
        out[b * 2 + 1] = e1 * inv;
    }
}

// ---------------------------------------------------------------------------
extern "C" void kernel_launch(void* const* d_in, const int* in_sizes, int n_in,
                              void* d_out, int out_size) {
    const float* x     = (const float*)d_in[0];
    const float* w1    = (const float*)d_in[1];
    const float* b1    = (const float*)d_in[2];
    const float* w2    = (const float*)d_in[3];
    const float* b2    = (const float*)d_in[4];
    const float* fc1_w = (const float*)d_in[5];
    const float* fc1_b = (const float*)d_in[6];
    const float* fc2_w = (const float*)d_in[7];
    const float* fc2_b = (const float*)d_in[8];
    const float* fc3_w = (const float*)d_in[9];
    const float* fc3_b = (const float*)d_in[10];
    const float* qw    = (const float*)d_in[11];
    float* out = (float*)d_out;

    cudaFuncSetAttribute(conv1_kernel, cudaFuncAttributeMaxDynamicSharedMemorySize, C1_SMEM_BYTES);
    cudaFuncSetAttribute(conv2_kernel, cudaFuncAttributeMaxDynamicSharedMemorySize, C2_SMEM_BYTES);

    conv1_kernel<<<dim3(4, 8, BATCH), 256, C1_SMEM_BYTES>>>(x, w1, b1);
    conv2_kernel<<<dim3(2, 4, BATCH), 256, C2_SMEM_BYTES>>>(w2, b2);
    fc1_mma_kernel<<<KSPLIT, 512>>>(fc1_w);
    reduce_kernel<<<240, 64>>>(fc1_b);
    head_kernel<<<BATCH, 128>>>(fc2_w, fc2_b, fc3_w, fc3_b, qw, out);
}